// round 6
// baseline (speedup 1.0000x reference)
#include <cuda_runtime.h>
#include <cuda_bf16.h>
#include <cuda_fp16.h>
#include <math.h>
#include <stdint.h>

// Problem constants
#define BB 4
#define LL 2048
#define DD 1024
#define HH 16
#define KVH 4
#define HD 64
#define ML (BB*LL)          // 8192 rows

// Scratch buffers (device globals; no allocation allowed)
__device__ float g_q[ML * HH * HD];     // 8192 x 1024
__device__ float g_k[ML * KVH * HD];    // 8192 x 256
__device__ float g_v[ML * KVH * HD];    // 8192 x 256
__device__ float g_attn[ML * HH * HD];  // 8192 x 1024

// ---------------------------------------------------------------------------
// mma helpers
// ---------------------------------------------------------------------------
__device__ __forceinline__ float f2tf32(float x) {
    uint32_t r;
    asm("cvt.rna.tf32.f32 %0, %1;" : "=r"(r) : "f"(x));
    return __uint_as_float(r);
}
__device__ __forceinline__ uint32_t fu(float x) { return __float_as_uint(x); }

__device__ __forceinline__ void mma_tf32(float c[4],
                                         const uint32_t a[4],
                                         const uint32_t b[2]) {
    asm volatile(
        "mma.sync.aligned.m16n8k8.row.col.f32.tf32.tf32.f32 "
        "{%0,%1,%2,%3}, {%4,%5,%6,%7}, {%8,%9}, {%0,%1,%2,%3};"
        : "+f"(c[0]), "+f"(c[1]), "+f"(c[2]), "+f"(c[3])
        : "r"(a[0]), "r"(a[1]), "r"(a[2]), "r"(a[3]), "r"(b[0]), "r"(b[1]));
}

__device__ __forceinline__ void mma_f16(float c[4], const uint32_t a[4],
                                        uint32_t b0, uint32_t b1) {
    asm volatile(
        "mma.sync.aligned.m16n8k16.row.col.f32.f16.f16.f32 "
        "{%0,%1,%2,%3}, {%4,%5,%6,%7}, {%8,%9}, {%0,%1,%2,%3};"
        : "+f"(c[0]), "+f"(c[1]), "+f"(c[2]), "+f"(c[3])
        : "r"(a[0]), "r"(a[1]), "r"(a[2]), "r"(a[3]), "r"(b0), "r"(b1));
}

__device__ __forceinline__ uint32_t packh2(float lo, float hi) {
    __half2 h = __floats2half2_rn(lo, hi);
    return *(uint32_t*)&h;
}

// ---------------------------------------------------------------------------
// TF32 tensor-core GEMM: C[M,N] = A[M,K] @ B[K,N]. (unchanged from R4)
// ---------------------------------------------------------------------------
#define GBM 128
#define GBN 128
#define GBK 32

__global__ __launch_bounds__(256, 1) void gemm_tf32(const float* __restrict__ A,
                                                    const float* __restrict__ B,
                                                    float* __restrict__ C,
                                                    int M, int N, int K) {
    __shared__ float As[GBM][36];
    __shared__ float Bs[GBK][136];

    const int tid  = threadIdx.x;
    const int bm   = blockIdx.y * GBM;
    const int bn   = blockIdx.x * GBN;
    const int lane = tid & 31;
    const int warp = tid >> 5;
    const int g    = lane >> 2;
    const int tig  = lane & 3;
    const int wm   = (warp & 3) * 32;
    const int wn   = (warp >> 2) * 64;

    const int a_k4 = tid & 7;
    const int a_m  = tid >> 3;
    const int b_n4 = tid & 31;
    const int b_k  = tid >> 5;

    float c[2][8][4];
#pragma unroll
    for (int mt = 0; mt < 2; ++mt)
#pragma unroll
        for (int nt = 0; nt < 8; ++nt)
#pragma unroll
            for (int i = 0; i < 4; ++i) c[mt][nt][i] = 0.f;

    const float* Abase = A + (size_t)(bm + a_m) * K + 4 * a_k4;
    const float* Bbase = B + (size_t)b_k * N + bn + 4 * b_n4;

    float4 Ar[4], Br[4];
#pragma unroll
    for (int i = 0; i < 4; ++i) Ar[i] = *(const float4*)(Abase + (size_t)(32 * i) * K);
#pragma unroll
    for (int i = 0; i < 4; ++i) Br[i] = *(const float4*)(Bbase + (size_t)(8 * i) * N);

    const int ktiles = K / GBK;
    for (int kt = 0; kt < ktiles; ++kt) {
#pragma unroll
        for (int i = 0; i < 4; ++i) {
            As[a_m + 32 * i][4 * a_k4 + 0] = f2tf32(Ar[i].x);
            As[a_m + 32 * i][4 * a_k4 + 1] = f2tf32(Ar[i].y);
            As[a_m + 32 * i][4 * a_k4 + 2] = f2tf32(Ar[i].z);
            As[a_m + 32 * i][4 * a_k4 + 3] = f2tf32(Ar[i].w);
        }
#pragma unroll
        for (int i = 0; i < 4; ++i) {
            float4 t;
            t.x = f2tf32(Br[i].x); t.y = f2tf32(Br[i].y);
            t.z = f2tf32(Br[i].z); t.w = f2tf32(Br[i].w);
            *(float4*)&Bs[b_k + 8 * i][4 * b_n4] = t;
        }
        __syncthreads();

        if (kt + 1 < ktiles) {
            const float* ap = Abase + (kt + 1) * GBK;
            const float* bp = Bbase + (size_t)(kt + 1) * GBK * N;
#pragma unroll
            for (int i = 0; i < 4; ++i) Ar[i] = *(const float4*)(ap + (size_t)(32 * i) * K);
#pragma unroll
            for (int i = 0; i < 4; ++i) Br[i] = *(const float4*)(bp + (size_t)(8 * i) * N);
        }

#pragma unroll
        for (int ks = 0; ks < 4; ++ks) {
            const int kk = ks * 8;
            uint32_t afr[2][4], bfr[8][2];
#pragma unroll
            for (int mt = 0; mt < 2; ++mt) {
                const int m0 = wm + 16 * mt;
                afr[mt][0] = fu(As[m0 + g    ][kk + tig    ]);
                afr[mt][1] = fu(As[m0 + g + 8][kk + tig    ]);
                afr[mt][2] = fu(As[m0 + g    ][kk + tig + 4]);
                afr[mt][3] = fu(As[m0 + g + 8][kk + tig + 4]);
            }
#pragma unroll
            for (int nt = 0; nt < 8; ++nt) {
                const int n0 = wn + 8 * nt;
                bfr[nt][0] = fu(Bs[kk + tig    ][n0 + g]);
                bfr[nt][1] = fu(Bs[kk + tig + 4][n0 + g]);
            }
#pragma unroll
            for (int mt = 0; mt < 2; ++mt)
#pragma unroll
                for (int nt = 0; nt < 8; ++nt)
                    mma_tf32(c[mt][nt], afr[mt], bfr[nt]);
        }
        __syncthreads();
    }

#pragma unroll
    for (int mt = 0; mt < 2; ++mt) {
        const int row0 = bm + wm + 16 * mt + g;
#pragma unroll
        for (int nt = 0; nt < 8; ++nt) {
            const int col = bn + wn + 8 * nt + 2 * tig;
            float2 lo; lo.x = c[mt][nt][0]; lo.y = c[mt][nt][1];
            float2 hi; hi.x = c[mt][nt][2]; hi.y = c[mt][nt][3];
            *(float2*)(C + (size_t)row0 * N + col)       = lo;
            *(float2*)(C + (size_t)(row0 + 8) * N + col) = hi;
        }
    }
}

// ---------------------------------------------------------------------------
// Interleaved RoPE (unchanged)
// ---------------------------------------------------------------------------
__global__ __launch_bounds__(256) void rope_kernel(float* __restrict__ t,
                                                   const float* __restrict__ cosf_,
                                                   const float* __restrict__ sinf_,
                                                   int total_pairs, int nheads) {
    int idx = blockIdx.x * blockDim.x + threadIdx.x;
    if (idx >= total_pairs) return;
    int i = idx & 31;
    int rest = idx >> 5;
    int bl = rest / nheads;
    int l = bl & (LL - 1);
    float c = cosf_[l * 32 + i];
    float s = sinf_[l * 32 + i];
    float2 p = *(float2*)(t + (size_t)idx * 2);
    float2 o;
    o.x = p.x * c - p.y * s;
    o.y = p.x * s + p.y * c;
    *(float2*)(t + (size_t)idx * 2) = o;
}

// ---------------------------------------------------------------------------
// Tensor-core flash attention (causal, GQA).
// Block: 128 queries of one (b,h); 4 warps x 32 rows (2 m-tiles each).
// KV tiles of 64 keys.  S via tf32 m16n8k8 (Kt transposed SMEM),
// P*V via f16 m16n8k16 (S-accum frags -> A-frags in registers, V pre-paired
// to half2).  Online softmax in base-2 domain (scale*log2e folded into Q).
// ---------------------------------------------------------------------------
__global__ __launch_bounds__(128) void attn_mma(const float* __restrict__ qg,
                                                const float* __restrict__ kg,
                                                const float* __restrict__ vg,
                                                float* __restrict__ og) {
    // SMEM overlay: phase0 Qs[128][68] f32 (34816B) ; mainloop Kt[64][72] f32
    // (18432B) + Vp[32][72] u32 (9216B).
    __shared__ __align__(16) char smraw[34816];
    float    (*Qs)[68] = (float(*)[68])smraw;
    float    (*Kt)[72] = (float(*)[72])smraw;
    uint32_t (*Vp)[72] = (uint32_t(*)[72])(smraw + 64 * 72 * 4);

    const int tid  = threadIdx.x;
    const int lane = tid & 31;
    const int warp = tid >> 5;
    const int g    = lane >> 2;
    const int tig  = lane & 3;
    const int qblk = blockIdx.x;
    const int h    = blockIdx.y;
    const int b    = blockIdx.z;
    const int kvh  = h >> 2;
    const int qb0  = qblk * 128;
    const int wl   = warp * 32;      // warp's local row base

    const float qscale = 0.125f * 1.4426950408889634f;   // (1/sqrt(64))*log2(e)

    // ---- Phase 0: stage Q tile (scaled, tf32) and read persistent A-frags
    {
        const float4* src = (const float4*)(qg + (((size_t)b * LL + qb0 + tid) * HH + h) * HD);
        float* dst = Qs[tid];
#pragma unroll
        for (int u = 0; u < 16; ++u) {
            float4 tv = src[u];
            dst[4 * u + 0] = f2tf32(tv.x * qscale);
            dst[4 * u + 1] = f2tf32(tv.y * qscale);
            dst[4 * u + 2] = f2tf32(tv.z * qscale);
            dst[4 * u + 3] = f2tf32(tv.w * qscale);
        }
    }
    __syncthreads();

    uint32_t qf[2][8][4];
#pragma unroll
    for (int mt = 0; mt < 2; ++mt)
#pragma unroll
        for (int ks = 0; ks < 8; ++ks) {
            const int r0 = wl + 16 * mt + g;
            qf[mt][ks][0] = fu(Qs[r0    ][8 * ks + tig    ]);
            qf[mt][ks][1] = fu(Qs[r0 + 8][8 * ks + tig    ]);
            qf[mt][ks][2] = fu(Qs[r0    ][8 * ks + tig + 4]);
            qf[mt][ks][3] = fu(Qs[r0 + 8][8 * ks + tig + 4]);
        }
    __syncthreads();   // Qs dead; Kt/Vp may now overwrite

    float oacc[2][8][4];
#pragma unroll
    for (int mt = 0; mt < 2; ++mt)
#pragma unroll
        for (int nt = 0; nt < 8; ++nt)
#pragma unroll
            for (int i = 0; i < 4; ++i) oacc[mt][nt][i] = 0.f;
    float mrow[2][2] = {{-INFINITY, -INFINITY}, {-INFINITY, -INFINITY}};
    float lrow[2][2] = {{0.f, 0.f}, {0.f, 0.f}};

    const int ntiles = 2 * (qblk + 1);

    for (int t = 0; t < ntiles; ++t) {
        const int j0 = t * 64;

        // ---- cooperative tile load: Kt (transposed, tf32) and Vp (paired f16)
        {
            const int j = tid >> 1, half = tid & 1;
            const float4* kp = (const float4*)(kg + (((size_t)b * LL + j0 + j) * KVH + kvh) * HD + 32 * half);
#pragma unroll
            for (int u = 0; u < 8; ++u) {
                float4 tv = kp[u];
                const int d = 32 * half + 4 * u;
                Kt[d + 0][j] = f2tf32(tv.x);
                Kt[d + 1][j] = f2tf32(tv.y);
                Kt[d + 2][j] = f2tf32(tv.z);
                Kt[d + 3][j] = f2tf32(tv.w);
            }
            const int p  = tid >> 2;
            const int qo = (tid & 3) * 16;
            const float* v0 = vg + (((size_t)b * LL + j0 + 2 * p) * KVH + kvh) * HD + qo;
            const float* v1 = v0 + (size_t)KVH * HD;
#pragma unroll
            for (int u = 0; u < 16; u += 4) {
                float4 a  = *(const float4*)(v0 + u);
                float4 bq = *(const float4*)(v1 + u);
                Vp[p][qo + u + 0] = packh2(a.x, bq.x);
                Vp[p][qo + u + 1] = packh2(a.y, bq.y);
                Vp[p][qo + u + 2] = packh2(a.z, bq.z);
                Vp[p][qo + u + 3] = packh2(a.w, bq.w);
            }
        }
        __syncthreads();

        if (j0 <= qb0 + wl + 31) {   // warp has visible rows in this tile
            // ---- S = Q @ K^T  (tf32)
            float sc[2][8][4];
#pragma unroll
            for (int mt = 0; mt < 2; ++mt)
#pragma unroll
                for (int nt = 0; nt < 8; ++nt)
#pragma unroll
                    for (int i = 0; i < 4; ++i) sc[mt][nt][i] = 0.f;

#pragma unroll
            for (int ks = 0; ks < 8; ++ks) {
#pragma unroll
                for (int nt = 0; nt < 8; ++nt) {
                    uint32_t bfr[2];
                    bfr[0] = fu(Kt[8 * ks + tig    ][8 * nt + g]);
                    bfr[1] = fu(Kt[8 * ks + tig + 4][8 * nt + g]);
                    mma_tf32(sc[0][nt], qf[0][ks], bfr);
                    mma_tf32(sc[1][nt], qf[1][ks], bfr);
                }
            }

            // ---- causal mask (only the diagonal tile needs it)
            if (j0 + 63 > qb0 + wl) {
#pragma unroll
                for (int mt = 0; mt < 2; ++mt) {
                    const int r0 = qb0 + wl + 16 * mt + g;
#pragma unroll
                    for (int nt = 0; nt < 8; ++nt) {
                        const int c0 = j0 + 8 * nt + 2 * tig;
                        if (c0     > r0    ) sc[mt][nt][0] = -INFINITY;
                        if (c0 + 1 > r0    ) sc[mt][nt][1] = -INFINITY;
                        if (c0     > r0 + 8) sc[mt][nt][2] = -INFINITY;
                        if (c0 + 1 > r0 + 8) sc[mt][nt][3] = -INFINITY;
                    }
                }
            }

            // ---- online softmax update (base-2)
#pragma unroll
            for (int mt = 0; mt < 2; ++mt) {
                float mx0 = -INFINITY, mx1 = -INFINITY;
#pragma unroll
                for (int nt = 0; nt < 8; ++nt) {
                    mx0 = fmaxf(mx0, fmaxf(sc[mt][nt][0], sc[mt][nt][1]));
                    mx1 = fmaxf(mx1, fmaxf(sc[mt][nt][2], sc[mt][nt][3]));
                }
                mx0 = fmaxf(mx0, __shfl_xor_sync(0xffffffffu, mx0, 1));
                mx0 = fmaxf(mx0, __shfl_xor_sync(0xffffffffu, mx0, 2));
                mx1 = fmaxf(mx1, __shfl_xor_sync(0xffffffffu, mx1, 1));
                mx1 = fmaxf(mx1, __shfl_xor_sync(0xffffffffu, mx1, 2));

                const float mnew0 = fmaxf(mrow[mt][0], mx0);
                const float mnew1 = fmaxf(mrow[mt][1], mx1);
                const float corr0 = exp2f(mrow[mt][0] - mnew0);
                const float corr1 = exp2f(mrow[mt][1] - mnew1);
                mrow[mt][0] = mnew0; mrow[mt][1] = mnew1;
                lrow[mt][0] *= corr0; lrow[mt][1] *= corr1;

                float sum0 = 0.f, sum1 = 0.f;
#pragma unroll
                for (int nt = 0; nt < 8; ++nt) {
                    oacc[mt][nt][0] *= corr0; oacc[mt][nt][1] *= corr0;
                    oacc[mt][nt][2] *= corr1; oacc[mt][nt][3] *= corr1;
                    sc[mt][nt][0] = exp2f(sc[mt][nt][0] - mnew0); sum0 += sc[mt][nt][0];
                    sc[mt][nt][1] = exp2f(sc[mt][nt][1] - mnew0); sum0 += sc[mt][nt][1];
                    sc[mt][nt][2] = exp2f(sc[mt][nt][2] - mnew1); sum1 += sc[mt][nt][2];
                    sc[mt][nt][3] = exp2f(sc[mt][nt][3] - mnew1); sum1 += sc[mt][nt][3];
                }
                lrow[mt][0] += sum0; lrow[mt][1] += sum1;
            }

            // ---- O += P @ V  (f16 mma; P frags repacked in registers)
#pragma unroll
            for (int ksp = 0; ksp < 4; ++ksp) {
                uint32_t pa[2][4];
#pragma unroll
                for (int mt = 0; mt < 2; ++mt) {
                    pa[mt][0] = packh2(sc[mt][2 * ksp    ][0], sc[mt][2 * ksp    ][1]);
                    pa[mt][1] = packh2(sc[mt][2 * ksp    ][2], sc[mt][2 * ksp    ][3]);
                    pa[mt][2] = packh2(sc[mt][2 * ksp + 1][0], sc[mt][2 * ksp + 1][1]);
                    pa[mt][3] = packh2(sc[mt][2 * ksp + 1][2], sc[mt][2 * ksp + 1][3]);
                }
#pragma unroll
                for (int nt = 0; nt < 8; ++nt) {
                    const uint32_t b0 = Vp[8 * ksp + tig    ][8 * nt + g];
                    const uint32_t b1 = Vp[8 * ksp + tig + 4][8 * nt + g];
                    mma_f16(oacc[0][nt], pa[0], b0, b1);
                    mma_f16(oacc[1][nt], pa[1], b0, b1);
                }
            }
        }
        __syncthreads();   // protect Kt/Vp before next tile's load
    }

    // ---- finalize: reduce l across the quad, normalize, store
#pragma unroll
    for (int mt = 0; mt < 2; ++mt) {
        float l0 = lrow[mt][0], l1 = lrow[mt][1];
        l0 += __shfl_xor_sync(0xffffffffu, l0, 1);
        l0 += __shfl_xor_sync(0xffffffffu, l0, 2);
        l1 += __shfl_xor_sync(0xffffffffu, l1, 1);
        l1 += __shfl_xor_sync(0xffffffffu, l1, 2);
        const float inv0 = 1.f / l0;
        const float inv1 = 1.f / l1;
        const int r0 = qb0 + wl + 16 * mt + g;
#pragma unroll
        for (int nt = 0; nt < 8; ++nt) {
            const int col = 8 * nt + 2 * tig;
            float2 w0; w0.x = oacc[mt][nt][0] * inv0; w0.y = oacc[mt][nt][1] * inv0;
            float2 w1; w1.x = oacc[mt][nt][2] * inv1; w1.y = oacc[mt][nt][3] * inv1;
            *(float2*)(og + (((size_t)b * LL + r0    ) * HH + h) * HD + col) = w0;
            *(float2*)(og + (((size_t)b * LL + r0 + 8) * HH + h) * HD + col) = w1;
        }
    }
}

// ---------------------------------------------------------------------------
// Launch
// ---------------------------------------------------------------------------
extern "C" void kernel_launch(void* const* d_in, const int* in_sizes, int n_in,
                              void* d_out, int out_size) {
    const float* x        = (const float*)d_in[0];
    const float* wq       = (const float*)d_in[1];
    const float* wk       = (const float*)d_in[2];
    const float* wv       = (const float*)d_in[3];
    const float* wo       = (const float*)d_in[4];
    const float* freqs_c  = (const float*)d_in[5];
    const float* freqs_s  = (const float*)d_in[6];
    // d_in[7] = mask: all-true by construction; causal mask handled in-kernel.
    float* out = (float*)d_out;

    float *qb, *kb, *vb, *ab;
    cudaGetSymbolAddress((void**)&qb, g_q);
    cudaGetSymbolAddress((void**)&kb, g_k);
    cudaGetSymbolAddress((void**)&vb, g_v);
    cudaGetSymbolAddress((void**)&ab, g_attn);

    // QKV projections (tf32 tensor cores)
    {
        dim3 gq(HH * HD / GBN, ML / GBM);     // (8, 64)
        gemm_tf32<<<gq, 256>>>(x, wq, qb, ML, HH * HD, DD);
        dim3 gk(KVH * HD / GBN, ML / GBM);    // (2, 64)
        gemm_tf32<<<gk, 256>>>(x, wk, kb, ML, KVH * HD, DD);
        gemm_tf32<<<gk, 256>>>(x, wv, vb, ML, KVH * HD, DD);
    }

    // RoPE on q and k
    {
        int qpairs = ML * HH * (HD / 2);
        int kpairs = ML * KVH * (HD / 2);
        rope_kernel<<<(qpairs + 255) / 256, 256>>>(qb, freqs_c, freqs_s, qpairs, HH);
        rope_kernel<<<(kpairs + 255) / 256, 256>>>(kb, freqs_c, freqs_s, kpairs, KVH);
    }

    // Attention (tensor cores)
    {
        dim3 ga(LL / 128, HH, BB);            // (16, 16, 4)
        attn_mma<<<ga, 128>>>(qb, kb, vb, ab);
    }

    // Output projection (tf32 tensor cores)
    {
        dim3 go(DD / GBN, ML / GBM);          // (8, 64)
        gemm_tf32<<<go, 256>>>(ab, wo, out, ML, DD, DD);
    }
}

// round 7
// speedup vs baseline: 1.1776x; 1.1776x over previous
#include <cuda_runtime.h>
#include <cuda_bf16.h>
#include <cuda_fp16.h>
#include <math.h>
#include <stdint.h>

// Problem constants
#define BB 4
#define LL 2048
#define DD 1024
#define HH 16
#define KVH 4
#define HD 64
#define ML (BB*LL)          // 8192 rows

// Scratch buffers (device globals; no allocation allowed)
__device__ float g_q[ML * HH * HD];     // 8192 x 1024
__device__ float g_k[ML * KVH * HD];    // 8192 x 256
__device__ float g_v[ML * KVH * HD];    // 8192 x 256
__device__ float g_attn[ML * HH * HD];  // 8192 x 1024

// ---------------------------------------------------------------------------
// mma helpers
// ---------------------------------------------------------------------------
__device__ __forceinline__ float f2tf32(float x) {
    uint32_t r;
    asm("cvt.rna.tf32.f32 %0, %1;" : "=r"(r) : "f"(x));
    return __uint_as_float(r);
}
__device__ __forceinline__ uint32_t fu(float x) { return __float_as_uint(x); }

__device__ __forceinline__ void mma_tf32(float c[4],
                                         const uint32_t a[4],
                                         const uint32_t b[2]) {
    asm volatile(
        "mma.sync.aligned.m16n8k8.row.col.f32.tf32.tf32.f32 "
        "{%0,%1,%2,%3}, {%4,%5,%6,%7}, {%8,%9}, {%0,%1,%2,%3};"
        : "+f"(c[0]), "+f"(c[1]), "+f"(c[2]), "+f"(c[3])
        : "r"(a[0]), "r"(a[1]), "r"(a[2]), "r"(a[3]), "r"(b[0]), "r"(b[1]));
}

__device__ __forceinline__ void mma_f16(float c[4], const uint32_t a[4],
                                        uint32_t b0, uint32_t b1) {
    asm volatile(
        "mma.sync.aligned.m16n8k16.row.col.f32.f16.f16.f32 "
        "{%0,%1,%2,%3}, {%4,%5,%6,%7}, {%8,%9}, {%0,%1,%2,%3};"
        : "+f"(c[0]), "+f"(c[1]), "+f"(c[2]), "+f"(c[3])
        : "r"(a[0]), "r"(a[1]), "r"(a[2]), "r"(a[3]), "r"(b0), "r"(b1));
}

__device__ __forceinline__ uint32_t packh2(float lo, float hi) {
    __half2 h = __floats2half2_rn(lo, hi);
    return *(uint32_t*)&h;
}

// ---------------------------------------------------------------------------
// F16 tensor-core GEMM: C[M,N] = A[M,K] @ B[K,N], f32 accumulate.
// 128x128 block tile, BK=32, 256 threads (8 warps, 4x2), warp tile 32x64.
// SMEM holds k-paired half2:
//   As2[m][k2]  (stride 20  -> a-frag banks 20g+tig, conflict-free)
//   Bs2[k2][n]  (stride 136 -> b-frag banks 8*tig+g, conflict-free)
// Optional fused RoPE on the epilogue (do_rope=1 for Q/K projections):
// output cols pair as (2i, 2i+1) within a 64-wide head; rotation applied
// per row using freqs[l = row mod LL][i].
// ---------------------------------------------------------------------------
#define GBM 128
#define GBN 128
#define GBK 32

__global__ __launch_bounds__(256, 1) void gemm_f16(const float* __restrict__ A,
                                                   const float* __restrict__ B,
                                                   float* __restrict__ C,
                                                   int M, int N, int K,
                                                   int do_rope,
                                                   const float* __restrict__ cosf_,
                                                   const float* __restrict__ sinf_) {
    __shared__ uint32_t As2[GBM][20];     // [m][k2] half2, 10240 B
    __shared__ uint32_t Bs2[GBK / 2][136];// [k2][n] half2,  8704 B

    const int tid  = threadIdx.x;
    const int bm   = blockIdx.y * GBM;
    const int bn   = blockIdx.x * GBN;
    const int lane = tid & 31;
    const int warp = tid >> 5;
    const int g    = lane >> 2;
    const int tig  = lane & 3;
    const int wm   = (warp & 3) * 32;
    const int wn   = (warp >> 2) * 64;

    // global-load mappings
    const int a_k4 = tid & 7;       // float4 index along K
    const int a_m  = tid >> 3;      // 0..31, rows a_m + 32*i
    const int b_k2 = tid >> 4;      // 0..15, k-pair row
    const int b_n8 = (tid & 15) * 8;// 8 n-values per thread

    float c[2][8][4];
#pragma unroll
    for (int mt = 0; mt < 2; ++mt)
#pragma unroll
        for (int nt = 0; nt < 8; ++nt)
#pragma unroll
            for (int i = 0; i < 4; ++i) c[mt][nt][i] = 0.f;

    const float* Abase = A + (size_t)(bm + a_m) * K + 4 * a_k4;
    const float* B0    = B + (size_t)(2 * b_k2) * N + bn + b_n8;
    const float* B1    = B0 + N;

    float4 Ar[4], Br0[2], Br1[2];

    // prologue: tile 0
#pragma unroll
    for (int i = 0; i < 4; ++i) Ar[i] = *(const float4*)(Abase + (size_t)(32 * i) * K);
    Br0[0] = *(const float4*)(B0);     Br0[1] = *(const float4*)(B0 + 4);
    Br1[0] = *(const float4*)(B1);     Br1[1] = *(const float4*)(B1 + 4);

    const int ktiles = K / GBK;
    for (int kt = 0; kt < ktiles; ++kt) {
        // stage to SMEM as half2 pairs along k
#pragma unroll
        for (int i = 0; i < 4; ++i) {
            As2[a_m + 32 * i][2 * a_k4 + 0] = packh2(Ar[i].x, Ar[i].y);
            As2[a_m + 32 * i][2 * a_k4 + 1] = packh2(Ar[i].z, Ar[i].w);
        }
        {
            uint4 w0, w1;
            w0.x = packh2(Br0[0].x, Br1[0].x);
            w0.y = packh2(Br0[0].y, Br1[0].y);
            w0.z = packh2(Br0[0].z, Br1[0].z);
            w0.w = packh2(Br0[0].w, Br1[0].w);
            w1.x = packh2(Br0[1].x, Br1[1].x);
            w1.y = packh2(Br0[1].y, Br1[1].y);
            w1.z = packh2(Br0[1].z, Br1[1].z);
            w1.w = packh2(Br0[1].w, Br1[1].w);
            *(uint4*)&Bs2[b_k2][b_n8]     = w0;
            *(uint4*)&Bs2[b_k2][b_n8 + 4] = w1;
        }
        __syncthreads();

        // prefetch next tile into registers
        if (kt + 1 < ktiles) {
            const float* ap = Abase + (kt + 1) * GBK;
            const float* bp0 = B0 + (size_t)(kt + 1) * GBK * N;
            const float* bp1 = bp0 + N;
#pragma unroll
            for (int i = 0; i < 4; ++i) Ar[i] = *(const float4*)(ap + (size_t)(32 * i) * K);
            Br0[0] = *(const float4*)(bp0);  Br0[1] = *(const float4*)(bp0 + 4);
            Br1[0] = *(const float4*)(bp1);  Br1[1] = *(const float4*)(bp1 + 4);
        }

        // 2 k16-steps
#pragma unroll
        for (int ks = 0; ks < 2; ++ks) {
            const int k2b = 8 * ks;
            uint32_t afr[2][4];
#pragma unroll
            for (int mt = 0; mt < 2; ++mt) {
                const int m0 = wm + 16 * mt;
                afr[mt][0] = As2[m0 + g    ][k2b + tig    ];
                afr[mt][1] = As2[m0 + g + 8][k2b + tig    ];
                afr[mt][2] = As2[m0 + g    ][k2b + tig + 4];
                afr[mt][3] = As2[m0 + g + 8][k2b + tig + 4];
            }
#pragma unroll
            for (int nt = 0; nt < 8; ++nt) {
                const int n0 = wn + 8 * nt;
                const uint32_t b0 = Bs2[k2b + tig    ][n0 + g];
                const uint32_t b1 = Bs2[k2b + tig + 4][n0 + g];
                mma_f16(c[0][nt], afr[0], b0, b1);
                mma_f16(c[1][nt], afr[1], b0, b1);
            }
        }
        __syncthreads();
    }

    // epilogue (optionally fused interleaved RoPE)
#pragma unroll
    for (int mt = 0; mt < 2; ++mt) {
        const int row0 = bm + wm + 16 * mt + g;
#pragma unroll
        for (int nt = 0; nt < 8; ++nt) {
            const int col = bn + wn + 8 * nt + 2 * tig;   // even
            float2 lo; lo.x = c[mt][nt][0]; lo.y = c[mt][nt][1];
            float2 hi; hi.x = c[mt][nt][2]; hi.y = c[mt][nt][3];
            if (do_rope) {
                const int i  = (col & (HD - 1)) >> 1;
                const int l0 = row0 & (LL - 1);
                const int l1 = (row0 + 8) & (LL - 1);
                float c0 = cosf_[l0 * 32 + i], s0 = sinf_[l0 * 32 + i];
                float c1 = cosf_[l1 * 32 + i], s1 = sinf_[l1 * 32 + i];
                float2 r0, r1;
                r0.x = lo.x * c0 - lo.y * s0;  r0.y = lo.x * s0 + lo.y * c0;
                r1.x = hi.x * c1 - hi.y * s1;  r1.y = hi.x * s1 + hi.y * c1;
                lo = r0; hi = r1;
            }
            *(float2*)(C + (size_t)row0 * N + col)       = lo;
            *(float2*)(C + (size_t)(row0 + 8) * N + col) = hi;
        }
    }
}

// ---------------------------------------------------------------------------
// Tensor-core flash attention (causal, GQA) — unchanged from R6.
// ---------------------------------------------------------------------------
__global__ __launch_bounds__(128) void attn_mma(const float* __restrict__ qg,
                                                const float* __restrict__ kg,
                                                const float* __restrict__ vg,
                                                float* __restrict__ og) {
    __shared__ __align__(16) char smraw[34816];
    float    (*Qs)[68] = (float(*)[68])smraw;
    float    (*Kt)[72] = (float(*)[72])smraw;
    uint32_t (*Vp)[72] = (uint32_t(*)[72])(smraw + 64 * 72 * 4);

    const int tid  = threadIdx.x;
    const int lane = tid & 31;
    const int warp = tid >> 5;
    const int g    = lane >> 2;
    const int tig  = lane & 3;
    const int qblk = blockIdx.x;
    const int h    = blockIdx.y;
    const int b    = blockIdx.z;
    const int kvh  = h >> 2;
    const int qb0  = qblk * 128;
    const int wl   = warp * 32;

    const float qscale = 0.125f * 1.4426950408889634f;   // (1/sqrt(64))*log2(e)

    {
        const float4* src = (const float4*)(qg + (((size_t)b * LL + qb0 + tid) * HH + h) * HD);
        float* dst = Qs[tid];
#pragma unroll
        for (int u = 0; u < 16; ++u) {
            float4 tv = src[u];
            dst[4 * u + 0] = f2tf32(tv.x * qscale);
            dst[4 * u + 1] = f2tf32(tv.y * qscale);
            dst[4 * u + 2] = f2tf32(tv.z * qscale);
            dst[4 * u + 3] = f2tf32(tv.w * qscale);
        }
    }
    __syncthreads();

    uint32_t qf[2][8][4];
#pragma unroll
    for (int mt = 0; mt < 2; ++mt)
#pragma unroll
        for (int ks = 0; ks < 8; ++ks) {
            const int r0 = wl + 16 * mt + g;
            qf[mt][ks][0] = fu(Qs[r0    ][8 * ks + tig    ]);
            qf[mt][ks][1] = fu(Qs[r0 + 8][8 * ks + tig    ]);
            qf[mt][ks][2] = fu(Qs[r0    ][8 * ks + tig + 4]);
            qf[mt][ks][3] = fu(Qs[r0 + 8][8 * ks + tig + 4]);
        }
    __syncthreads();

    float oacc[2][8][4];
#pragma unroll
    for (int mt = 0; mt < 2; ++mt)
#pragma unroll
        for (int nt = 0; nt < 8; ++nt)
#pragma unroll
            for (int i = 0; i < 4; ++i) oacc[mt][nt][i] = 0.f;
    float mrow[2][2] = {{-INFINITY, -INFINITY}, {-INFINITY, -INFINITY}};
    float lrow[2][2] = {{0.f, 0.f}, {0.f, 0.f}};

    const int ntiles = 2 * (qblk + 1);

    for (int t = 0; t < ntiles; ++t) {
        const int j0 = t * 64;
        {
            const int j = tid >> 1, half = tid & 1;
            const float4* kp = (const float4*)(kg + (((size_t)b * LL + j0 + j) * KVH + kvh) * HD + 32 * half);
#pragma unroll
            for (int u = 0; u < 8; ++u) {
                float4 tv = kp[u];
                const int d = 32 * half + 4 * u;
                Kt[d + 0][j] = f2tf32(tv.x);
                Kt[d + 1][j] = f2tf32(tv.y);
                Kt[d + 2][j] = f2tf32(tv.z);
                Kt[d + 3][j] = f2tf32(tv.w);
            }
            const int p  = tid >> 2;
            const int qo = (tid & 3) * 16;
            const float* v0 = vg + (((size_t)b * LL + j0 + 2 * p) * KVH + kvh) * HD + qo;
            const float* v1 = v0 + (size_t)KVH * HD;
#pragma unroll
            for (int u = 0; u < 16; u += 4) {
                float4 a  = *(const float4*)(v0 + u);
                float4 bq = *(const float4*)(v1 + u);
                Vp[p][qo + u + 0] = packh2(a.x, bq.x);
                Vp[p][qo + u + 1] = packh2(a.y, bq.y);
                Vp[p][qo + u + 2] = packh2(a.z, bq.z);
                Vp[p][qo + u + 3] = packh2(a.w, bq.w);
            }
        }
        __syncthreads();

        if (j0 <= qb0 + wl + 31) {
            float sc[2][8][4];
#pragma unroll
            for (int mt = 0; mt < 2; ++mt)
#pragma unroll
                for (int nt = 0; nt < 8; ++nt)
#pragma unroll
                    for (int i = 0; i < 4; ++i) sc[mt][nt][i] = 0.f;

#pragma unroll
            for (int ks = 0; ks < 8; ++ks) {
#pragma unroll
                for (int nt = 0; nt < 8; ++nt) {
                    uint32_t bfr[2];
                    bfr[0] = fu(Kt[8 * ks + tig    ][8 * nt + g]);
                    bfr[1] = fu(Kt[8 * ks + tig + 4][8 * nt + g]);
                    mma_tf32(sc[0][nt], qf[0][ks], bfr);
                    mma_tf32(sc[1][nt], qf[1][ks], bfr);
                }
            }

            if (j0 + 63 > qb0 + wl) {
#pragma unroll
                for (int mt = 0; mt < 2; ++mt) {
                    const int r0 = qb0 + wl + 16 * mt + g;
#pragma unroll
                    for (int nt = 0; nt < 8; ++nt) {
                        const int c0 = j0 + 8 * nt + 2 * tig;
                        if (c0     > r0    ) sc[mt][nt][0] = -INFINITY;
                        if (c0 + 1 > r0    ) sc[mt][nt][1] = -INFINITY;
                        if (c0     > r0 + 8) sc[mt][nt][2] = -INFINITY;
                        if (c0 + 1 > r0 + 8) sc[mt][nt][3] = -INFINITY;
                    }
                }
            }

#pragma unroll
            for (int mt = 0; mt < 2; ++mt) {
                float mx0 = -INFINITY, mx1 = -INFINITY;
#pragma unroll
                for (int nt = 0; nt < 8; ++nt) {
                    mx0 = fmaxf(mx0, fmaxf(sc[mt][nt][0], sc[mt][nt][1]));
                    mx1 = fmaxf(mx1, fmaxf(sc[mt][nt][2], sc[mt][nt][3]));
                }
                mx0 = fmaxf(mx0, __shfl_xor_sync(0xffffffffu, mx0, 1));
                mx0 = fmaxf(mx0, __shfl_xor_sync(0xffffffffu, mx0, 2));
                mx1 = fmaxf(mx1, __shfl_xor_sync(0xffffffffu, mx1, 1));
                mx1 = fmaxf(mx1, __shfl_xor_sync(0xffffffffu, mx1, 2));

                const float mnew0 = fmaxf(mrow[mt][0], mx0);
                const float mnew1 = fmaxf(mrow[mt][1], mx1);
                const float corr0 = exp2f(mrow[mt][0] - mnew0);
                const float corr1 = exp2f(mrow[mt][1] - mnew1);
                mrow[mt][0] = mnew0; mrow[mt][1] = mnew1;
                lrow[mt][0] *= corr0; lrow[mt][1] *= corr1;

                float sum0 = 0.f, sum1 = 0.f;
#pragma unroll
                for (int nt = 0; nt < 8; ++nt) {
                    oacc[mt][nt][0] *= corr0; oacc[mt][nt][1] *= corr0;
                    oacc[mt][nt][2] *= corr1; oacc[mt][nt][3] *= corr1;
                    sc[mt][nt][0] = exp2f(sc[mt][nt][0] - mnew0); sum0 += sc[mt][nt][0];
                    sc[mt][nt][1] = exp2f(sc[mt][nt][1] - mnew0); sum0 += sc[mt][nt][1];
                    sc[mt][nt][2] = exp2f(sc[mt][nt][2] - mnew1); sum1 += sc[mt][nt][2];
                    sc[mt][nt][3] = exp2f(sc[mt][nt][3] - mnew1); sum1 += sc[mt][nt][3];
                }
                lrow[mt][0] += sum0; lrow[mt][1] += sum1;
            }

#pragma unroll
            for (int ksp = 0; ksp < 4; ++ksp) {
                uint32_t pa[2][4];
#pragma unroll
                for (int mt = 0; mt < 2; ++mt) {
                    pa[mt][0] = packh2(sc[mt][2 * ksp    ][0], sc[mt][2 * ksp    ][1]);
                    pa[mt][1] = packh2(sc[mt][2 * ksp    ][2], sc[mt][2 * ksp    ][3]);
                    pa[mt][2] = packh2(sc[mt][2 * ksp + 1][0], sc[mt][2 * ksp + 1][1]);
                    pa[mt][3] = packh2(sc[mt][2 * ksp + 1][2], sc[mt][2 * ksp + 1][3]);
                }
#pragma unroll
                for (int nt = 0; nt < 8; ++nt) {
                    const uint32_t b0 = Vp[8 * ksp + tig    ][8 * nt + g];
                    const uint32_t b1 = Vp[8 * ksp + tig + 4][8 * nt + g];
                    mma_f16(oacc[0][nt], pa[0], b0, b1);
                    mma_f16(oacc[1][nt], pa[1], b0, b1);
                }
            }
        }
        __syncthreads();
    }

#pragma unroll
    for (int mt = 0; mt < 2; ++mt) {
        float l0 = lrow[mt][0], l1 = lrow[mt][1];
        l0 += __shfl_xor_sync(0xffffffffu, l0, 1);
        l0 += __shfl_xor_sync(0xffffffffu, l0, 2);
        l1 += __shfl_xor_sync(0xffffffffu, l1, 1);
        l1 += __shfl_xor_sync(0xffffffffu, l1, 2);
        const float inv0 = 1.f / l0;
        const float inv1 = 1.f / l1;
        const int r0 = qb0 + wl + 16 * mt + g;
#pragma unroll
        for (int nt = 0; nt < 8; ++nt) {
            const int col = 8 * nt + 2 * tig;
            float2 w0; w0.x = oacc[mt][nt][0] * inv0; w0.y = oacc[mt][nt][1] * inv0;
            float2 w1; w1.x = oacc[mt][nt][2] * inv1; w1.y = oacc[mt][nt][3] * inv1;
            *(float2*)(og + (((size_t)b * LL + r0    ) * HH + h) * HD + col) = w0;
            *(float2*)(og + (((size_t)b * LL + r0 + 8) * HH + h) * HD + col) = w1;
        }
    }
}

// ---------------------------------------------------------------------------
// Launch
// ---------------------------------------------------------------------------
extern "C" void kernel_launch(void* const* d_in, const int* in_sizes, int n_in,
                              void* d_out, int out_size) {
    const float* x        = (const float*)d_in[0];
    const float* wq       = (const float*)d_in[1];
    const float* wk       = (const float*)d_in[2];
    const float* wv       = (const float*)d_in[3];
    const float* wo       = (const float*)d_in[4];
    const float* freqs_c  = (const float*)d_in[5];
    const float* freqs_s  = (const float*)d_in[6];
    // d_in[7] = mask: all-true by construction; causal mask handled in-kernel.
    float* out = (float*)d_out;

    float *qb, *kb, *vb, *ab;
    cudaGetSymbolAddress((void**)&qb, g_q);
    cudaGetSymbolAddress((void**)&kb, g_k);
    cudaGetSymbolAddress((void**)&vb, g_v);
    cudaGetSymbolAddress((void**)&ab, g_attn);

    // QKV projections (f16 tensor cores; RoPE fused into Q/K epilogues)
    {
        dim3 gq(HH * HD / GBN, ML / GBM);     // (8, 64)
        gemm_f16<<<gq, 256>>>(x, wq, qb, ML, HH * HD, DD, 1, freqs_c, freqs_s);
        dim3 gk(KVH * HD / GBN, ML / GBM);    // (2, 64)
        gemm_f16<<<gk, 256>>>(x, wk, kb, ML, KVH * HD, DD, 1, freqs_c, freqs_s);
        gemm_f16<<<gk, 256>>>(x, wv, vb, ML, KVH * HD, DD, 0, nullptr, nullptr);
    }

    // Attention (tensor cores)
    {
        dim3 ga(LL / 128, HH, BB);            // (16, 16, 4)
        attn_mma<<<ga, 128>>>(qb, kb, vb, ab);
    }

    // Output projection (f16 tensor cores)
    {
        dim3 go(DD / GBN, ML / GBM);          // (8, 64)
        gemm_f16<<<go, 256>>>(ab, wo, out, ML, DD, DD, 0, nullptr, nullptr);
    }
}

// round 8
// speedup vs baseline: 1.2824x; 1.0890x over previous
#include <cuda_runtime.h>
#include <cuda_bf16.h>
#include <cuda_fp16.h>
#include <math.h>
#include <stdint.h>

// Problem constants
#define BB 4
#define LL 2048
#define DD 1024
#define HH 16
#define KVH 4
#define HD 64
#define ML (BB*LL)          // 8192 rows

// Scratch buffers (device globals; no allocation allowed)
__device__ float g_q[ML * HH * HD];     // 8192 x 1024
__device__ float g_k[ML * KVH * HD];    // 8192 x 256
__device__ float g_v[ML * KVH * HD];    // 8192 x 256
__device__ float g_attn[ML * HH * HD];  // 8192 x 1024

// ---------------------------------------------------------------------------
// mma helpers
// ---------------------------------------------------------------------------
__device__ __forceinline__ uint32_t fu(float x) { return __float_as_uint(x); }

__device__ __forceinline__ void mma_f16(float c[4], const uint32_t a[4],
                                        uint32_t b0, uint32_t b1) {
    asm volatile(
        "mma.sync.aligned.m16n8k16.row.col.f32.f16.f16.f32 "
        "{%0,%1,%2,%3}, {%4,%5,%6,%7}, {%8,%9}, {%0,%1,%2,%3};"
        : "+f"(c[0]), "+f"(c[1]), "+f"(c[2]), "+f"(c[3])
        : "r"(a[0]), "r"(a[1]), "r"(a[2]), "r"(a[3]), "r"(b0), "r"(b1));
}

__device__ __forceinline__ uint32_t packh2(float lo, float hi) {
    __half2 h = __floats2half2_rn(lo, hi);
    return *(uint32_t*)&h;
}

// ---------------------------------------------------------------------------
// F16 tensor-core GEMM (unchanged from R7): C[M,N] = A[M,K] @ B[K,N].
// 128x128 block tile, BK=32, 256 threads, warp tile 32x64, f32 accumulate.
// Optional fused interleaved RoPE on the epilogue.
// ---------------------------------------------------------------------------
#define GBM 128
#define GBN 128
#define GBK 32

__global__ __launch_bounds__(256, 1) void gemm_f16(const float* __restrict__ A,
                                                   const float* __restrict__ B,
                                                   float* __restrict__ C,
                                                   int M, int N, int K,
                                                   int do_rope,
                                                   const float* __restrict__ cosf_,
                                                   const float* __restrict__ sinf_) {
    __shared__ uint32_t As2[GBM][20];
    __shared__ uint32_t Bs2[GBK / 2][136];

    const int tid  = threadIdx.x;
    const int bm   = blockIdx.y * GBM;
    const int bn   = blockIdx.x * GBN;
    const int lane = tid & 31;
    const int warp = tid >> 5;
    const int g    = lane >> 2;
    const int tig  = lane & 3;
    const int wm   = (warp & 3) * 32;
    const int wn   = (warp >> 2) * 64;

    const int a_k4 = tid & 7;
    const int a_m  = tid >> 3;
    const int b_k2 = tid >> 4;
    const int b_n8 = (tid & 15) * 8;

    float c[2][8][4];
#pragma unroll
    for (int mt = 0; mt < 2; ++mt)
#pragma unroll
        for (int nt = 0; nt < 8; ++nt)
#pragma unroll
            for (int i = 0; i < 4; ++i) c[mt][nt][i] = 0.f;

    const float* Abase = A + (size_t)(bm + a_m) * K + 4 * a_k4;
    const float* B0    = B + (size_t)(2 * b_k2) * N + bn + b_n8;
    const float* B1    = B0 + N;

    float4 Ar[4], Br0[2], Br1[2];
#pragma unroll
    for (int i = 0; i < 4; ++i) Ar[i] = *(const float4*)(Abase + (size_t)(32 * i) * K);
    Br0[0] = *(const float4*)(B0);     Br0[1] = *(const float4*)(B0 + 4);
    Br1[0] = *(const float4*)(B1);     Br1[1] = *(const float4*)(B1 + 4);

    const int ktiles = K / GBK;
    for (int kt = 0; kt < ktiles; ++kt) {
#pragma unroll
        for (int i = 0; i < 4; ++i) {
            As2[a_m + 32 * i][2 * a_k4 + 0] = packh2(Ar[i].x, Ar[i].y);
            As2[a_m + 32 * i][2 * a_k4 + 1] = packh2(Ar[i].z, Ar[i].w);
        }
        {
            uint4 w0, w1;
            w0.x = packh2(Br0[0].x, Br1[0].x);
            w0.y = packh2(Br0[0].y, Br1[0].y);
            w0.z = packh2(Br0[0].z, Br1[0].z);
            w0.w = packh2(Br0[0].w, Br1[0].w);
            w1.x = packh2(Br0[1].x, Br1[1].x);
            w1.y = packh2(Br0[1].y, Br1[1].y);
            w1.z = packh2(Br0[1].z, Br1[1].z);
            w1.w = packh2(Br0[1].w, Br1[1].w);
            *(uint4*)&Bs2[b_k2][b_n8]     = w0;
            *(uint4*)&Bs2[b_k2][b_n8 + 4] = w1;
        }
        __syncthreads();

        if (kt + 1 < ktiles) {
            const float* ap = Abase + (kt + 1) * GBK;
            const float* bp0 = B0 + (size_t)(kt + 1) * GBK * N;
            const float* bp1 = bp0 + N;
#pragma unroll
            for (int i = 0; i < 4; ++i) Ar[i] = *(const float4*)(ap + (size_t)(32 * i) * K);
            Br0[0] = *(const float4*)(bp0);  Br0[1] = *(const float4*)(bp0 + 4);
            Br1[0] = *(const float4*)(bp1);  Br1[1] = *(const float4*)(bp1 + 4);
        }

#pragma unroll
        for (int ks = 0; ks < 2; ++ks) {
            const int k2b = 8 * ks;
            uint32_t afr[2][4];
#pragma unroll
            for (int mt = 0; mt < 2; ++mt) {
                const int m0 = wm + 16 * mt;
                afr[mt][0] = As2[m0 + g    ][k2b + tig    ];
                afr[mt][1] = As2[m0 + g + 8][k2b + tig    ];
                afr[mt][2] = As2[m0 + g    ][k2b + tig + 4];
                afr[mt][3] = As2[m0 + g + 8][k2b + tig + 4];
            }
#pragma unroll
            for (int nt = 0; nt < 8; ++nt) {
                const int n0 = wn + 8 * nt;
                const uint32_t b0 = Bs2[k2b + tig    ][n0 + g];
                const uint32_t b1 = Bs2[k2b + tig + 4][n0 + g];
                mma_f16(c[0][nt], afr[0], b0, b1);
                mma_f16(c[1][nt], afr[1], b0, b1);
            }
        }
        __syncthreads();
    }

#pragma unroll
    for (int mt = 0; mt < 2; ++mt) {
        const int row0 = bm + wm + 16 * mt + g;
#pragma unroll
        for (int nt = 0; nt < 8; ++nt) {
            const int col = bn + wn + 8 * nt + 2 * tig;
            float2 lo; lo.x = c[mt][nt][0]; lo.y = c[mt][nt][1];
            float2 hi; hi.x = c[mt][nt][2]; hi.y = c[mt][nt][3];
            if (do_rope) {
                const int i  = (col & (HD - 1)) >> 1;
                const int l0 = row0 & (LL - 1);
                const int l1 = (row0 + 8) & (LL - 1);
                float c0 = cosf_[l0 * 32 + i], s0 = sinf_[l0 * 32 + i];
                float c1 = cosf_[l1 * 32 + i], s1 = sinf_[l1 * 32 + i];
                float2 r0, r1;
                r0.x = lo.x * c0 - lo.y * s0;  r0.y = lo.x * s0 + lo.y * c0;
                r1.x = hi.x * c1 - hi.y * s1;  r1.y = hi.x * s1 + hi.y * c1;
                lo = r0; hi = r1;
            }
            *(float2*)(C + (size_t)row0 * N + col)       = lo;
            *(float2*)(C + (size_t)(row0 + 8) * N + col) = hi;
        }
    }
}

// ---------------------------------------------------------------------------
// F16 tensor-core flash attention (causal, GQA).
// Block: 256 threads = 8 warps; 128 queries; each warp owns a 16-row m-tile.
// KV tiles of 64 keys. Both S=QK^T and O+=PV via f16 m16n8k16, f32 accum.
// Q staged once as scaled half2 d-pairs (Qp, stride 36: banks 4g+tig).
// K staged as d-paired half2 transposed (Kp[d2][key], stride 72: b-frag banks
// 8*tig+g conflict-free). V as key-paired half2 (Vp[key2][d], stride 72).
// Online softmax in base-2 (scale*log2e folded into Q before f16 quantize).
// ---------------------------------------------------------------------------
__global__ __launch_bounds__(256) void attn_mma(const float* __restrict__ qg,
                                                const float* __restrict__ kg,
                                                const float* __restrict__ vg,
                                                float* __restrict__ og) {
    // Overlay: phase0 Qp[128][36] u32 (18432B); mainloop Kp[32][72] (9216B)
    // + Vp[32][72] (9216B).
    __shared__ __align__(16) uint32_t smraw[128 * 36];
    uint32_t (*Qp)[36] = (uint32_t(*)[36])smraw;
    uint32_t (*Kp)[72] = (uint32_t(*)[72])smraw;
    uint32_t (*Vp)[72] = (uint32_t(*)[72])(smraw + 32 * 72);

    const int tid  = threadIdx.x;
    const int lane = tid & 31;
    const int warp = tid >> 5;
    const int g    = lane >> 2;
    const int tig  = lane & 3;
    const int qblk = blockIdx.x;
    const int h    = blockIdx.y;
    const int b    = blockIdx.z;
    const int kvh  = h >> 2;
    const int qb0  = qblk * 128;
    const int wl   = warp * 16;          // warp's local row base

    const float qscale = 0.125f * 1.4426950408889634f;   // (1/sqrt(64))*log2(e)

    // ---- Phase 0: stage Q (scaled, f16 pairs); read persistent A-frags
    {
        const int row = tid >> 1, half = tid & 1;
        const float4* src = (const float4*)(qg + (((size_t)b * LL + qb0 + row) * HH + h) * HD + 32 * half);
        uint32_t* dst = &Qp[row][16 * half];
#pragma unroll
        for (int u = 0; u < 8; ++u) {
            float4 tv = src[u];
            dst[2 * u + 0] = packh2(tv.x * qscale, tv.y * qscale);
            dst[2 * u + 1] = packh2(tv.z * qscale, tv.w * qscale);
        }
    }
    __syncthreads();

    uint32_t qf[4][4];
#pragma unroll
    for (int ks = 0; ks < 4; ++ks) {
        qf[ks][0] = Qp[wl + g    ][8 * ks + tig    ];
        qf[ks][1] = Qp[wl + g + 8][8 * ks + tig    ];
        qf[ks][2] = Qp[wl + g    ][8 * ks + tig + 4];
        qf[ks][3] = Qp[wl + g + 8][8 * ks + tig + 4];
    }
    __syncthreads();   // Qp dead; Kp/Vp may overwrite

    float oacc[8][4];
#pragma unroll
    for (int nt = 0; nt < 8; ++nt)
#pragma unroll
        for (int i = 0; i < 4; ++i) oacc[nt][i] = 0.f;
    float mrow0 = -INFINITY, mrow1 = -INFINITY;
    float lrow0 = 0.f, lrow1 = 0.f;

    const int ntiles = 2 * (qblk + 1);

    for (int t = 0; t < ntiles; ++t) {
        const int j0 = t * 64;

        // ---- stage K tile: Kp[d2][j] = half2(K[j][2*d2], K[j][2*d2+1])
        {
            const int j = tid & 63, seg = tid >> 6;           // seg: 16-d slab
            const float4* kp = (const float4*)(kg + (((size_t)b * LL + j0 + j) * KVH + kvh) * HD + 16 * seg);
#pragma unroll
            for (int u = 0; u < 4; ++u) {
                float4 tv = kp[u];
                Kp[8 * seg + 2 * u    ][j] = packh2(tv.x, tv.y);
                Kp[8 * seg + 2 * u + 1][j] = packh2(tv.z, tv.w);
            }
        }
        // ---- stage V tile: Vp[p][d] = half2(V[2p][d], V[2p+1][d])
        {
            const int p = tid >> 3, d0 = (tid & 7) * 8;
            const float* v0 = vg + (((size_t)b * LL + j0 + 2 * p) * KVH + kvh) * HD + d0;
            const float* v1 = v0 + (size_t)KVH * HD;
            uint4 w0, w1;
            {
                float4 a = *(const float4*)(v0);
                float4 bq = *(const float4*)(v1);
                w0.x = packh2(a.x, bq.x); w0.y = packh2(a.y, bq.y);
                w0.z = packh2(a.z, bq.z); w0.w = packh2(a.w, bq.w);
            }
            {
                float4 a = *(const float4*)(v0 + 4);
                float4 bq = *(const float4*)(v1 + 4);
                w1.x = packh2(a.x, bq.x); w1.y = packh2(a.y, bq.y);
                w1.z = packh2(a.z, bq.z); w1.w = packh2(a.w, bq.w);
            }
            *(uint4*)&Vp[p][d0]     = w0;
            *(uint4*)&Vp[p][d0 + 4] = w1;
        }
        __syncthreads();

        if (j0 <= qb0 + wl + 15) {     // warp has visible rows in this tile
            // ---- S = Q @ K^T (f16)
            float sc[8][4];
#pragma unroll
            for (int nt = 0; nt < 8; ++nt)
#pragma unroll
                for (int i = 0; i < 4; ++i) sc[nt][i] = 0.f;

#pragma unroll
            for (int ks = 0; ks < 4; ++ks)
#pragma unroll
                for (int nt = 0; nt < 8; ++nt) {
                    const uint32_t b0 = Kp[8 * ks + tig    ][8 * nt + g];
                    const uint32_t b1 = Kp[8 * ks + tig + 4][8 * nt + g];
                    mma_f16(sc[nt], qf[ks], b0, b1);
                }

            // ---- causal mask (diagonal tile only)
            if (j0 + 63 > qb0 + wl) {
                const int r0 = qb0 + wl + g;
#pragma unroll
                for (int nt = 0; nt < 8; ++nt) {
                    const int c0 = j0 + 8 * nt + 2 * tig;
                    if (c0     > r0    ) sc[nt][0] = -INFINITY;
                    if (c0 + 1 > r0    ) sc[nt][1] = -INFINITY;
                    if (c0     > r0 + 8) sc[nt][2] = -INFINITY;
                    if (c0 + 1 > r0 + 8) sc[nt][3] = -INFINITY;
                }
            }

            // ---- online softmax (base-2)
            float mx0 = -INFINITY, mx1 = -INFINITY;
#pragma unroll
            for (int nt = 0; nt < 8; ++nt) {
                mx0 = fmaxf(mx0, fmaxf(sc[nt][0], sc[nt][1]));
                mx1 = fmaxf(mx1, fmaxf(sc[nt][2], sc[nt][3]));
            }
            mx0 = fmaxf(mx0, __shfl_xor_sync(0xffffffffu, mx0, 1));
            mx0 = fmaxf(mx0, __shfl_xor_sync(0xffffffffu, mx0, 2));
            mx1 = fmaxf(mx1, __shfl_xor_sync(0xffffffffu, mx1, 1));
            mx1 = fmaxf(mx1, __shfl_xor_sync(0xffffffffu, mx1, 2));

            const float mnew0 = fmaxf(mrow0, mx0);
            const float mnew1 = fmaxf(mrow1, mx1);
            const float corr0 = exp2f(mrow0 - mnew0);
            const float corr1 = exp2f(mrow1 - mnew1);
            mrow0 = mnew0; mrow1 = mnew1;
            lrow0 *= corr0; lrow1 *= corr1;

            float sum0 = 0.f, sum1 = 0.f;
#pragma unroll
            for (int nt = 0; nt < 8; ++nt) {
                oacc[nt][0] *= corr0; oacc[nt][1] *= corr0;
                oacc[nt][2] *= corr1; oacc[nt][3] *= corr1;
                sc[nt][0] = exp2f(sc[nt][0] - mnew0); sum0 += sc[nt][0];
                sc[nt][1] = exp2f(sc[nt][1] - mnew0); sum0 += sc[nt][1];
                sc[nt][2] = exp2f(sc[nt][2] - mnew1); sum1 += sc[nt][2];
                sc[nt][3] = exp2f(sc[nt][3] - mnew1); sum1 += sc[nt][3];
            }
            lrow0 += sum0; lrow1 += sum1;

            // ---- O += P @ V (f16; P frags repacked in registers)
#pragma unroll
            for (int ksp = 0; ksp < 4; ++ksp) {
                uint32_t pa[4];
                pa[0] = packh2(sc[2 * ksp    ][0], sc[2 * ksp    ][1]);
                pa[1] = packh2(sc[2 * ksp    ][2], sc[2 * ksp    ][3]);
                pa[2] = packh2(sc[2 * ksp + 1][0], sc[2 * ksp + 1][1]);
                pa[3] = packh2(sc[2 * ksp + 1][2], sc[2 * ksp + 1][3]);
#pragma unroll
                for (int nt = 0; nt < 8; ++nt) {
                    const uint32_t b0 = Vp[8 * ksp + tig    ][8 * nt + g];
                    const uint32_t b1 = Vp[8 * ksp + tig + 4][8 * nt + g];
                    mma_f16(oacc[nt], pa, b0, b1);
                }
            }
        }
        __syncthreads();   // protect Kp/Vp before next tile's load
    }

    // ---- finalize
    lrow0 += __shfl_xor_sync(0xffffffffu, lrow0, 1);
    lrow0 += __shfl_xor_sync(0xffffffffu, lrow0, 2);
    lrow1 += __shfl_xor_sync(0xffffffffu, lrow1, 1);
    lrow1 += __shfl_xor_sync(0xffffffffu, lrow1, 2);
    const float inv0 = 1.f / lrow0;
    const float inv1 = 1.f / lrow1;
    const int r0 = qb0 + wl + g;
#pragma unroll
    for (int nt = 0; nt < 8; ++nt) {
        const int col = 8 * nt + 2 * tig;
        float2 w0; w0.x = oacc[nt][0] * inv0; w0.y = oacc[nt][1] * inv0;
        float2 w1; w1.x = oacc[nt][2] * inv1; w1.y = oacc[nt][3] * inv1;
        *(float2*)(og + (((size_t)b * LL + r0    ) * HH + h) * HD + col) = w0;
        *(float2*)(og + (((size_t)b * LL + r0 + 8) * HH + h) * HD + col) = w1;
    }
}

// ---------------------------------------------------------------------------
// Launch
// ---------------------------------------------------------------------------
extern "C" void kernel_launch(void* const* d_in, const int* in_sizes, int n_in,
                              void* d_out, int out_size) {
    const float* x        = (const float*)d_in[0];
    const float* wq       = (const float*)d_in[1];
    const float* wk       = (const float*)d_in[2];
    const float* wv       = (const float*)d_in[3];
    const float* wo       = (const float*)d_in[4];
    const float* freqs_c  = (const float*)d_in[5];
    const float* freqs_s  = (const float*)d_in[6];
    // d_in[7] = mask: all-true by construction; causal mask handled in-kernel.
    float* out = (float*)d_out;

    float *qb, *kb, *vb, *ab;
    cudaGetSymbolAddress((void**)&qb, g_q);
    cudaGetSymbolAddress((void**)&kb, g_k);
    cudaGetSymbolAddress((void**)&vb, g_v);
    cudaGetSymbolAddress((void**)&ab, g_attn);

    // QKV projections (f16 tensor cores; RoPE fused into Q/K epilogues)
    {
        dim3 gq(HH * HD / GBN, ML / GBM);     // (8, 64)
        gemm_f16<<<gq, 256>>>(x, wq, qb, ML, HH * HD, DD, 1, freqs_c, freqs_s);
        dim3 gk(KVH * HD / GBN, ML / GBM);    // (2, 64)
        gemm_f16<<<gk, 256>>>(x, wk, kb, ML, KVH * HD, DD, 1, freqs_c, freqs_s);
        gemm_f16<<<gk, 256>>>(x, wv, vb, ML, KVH * HD, DD, 0, nullptr, nullptr);
    }

    // Attention (f16 tensor cores)
    {
        dim3 ga(LL / 128, HH, BB);            // (16, 16, 4)
        attn_mma<<<ga, 256>>>(qb, kb, vb, ab);
    }

    // Output projection (f16 tensor cores)
    {
        dim3 go(DD / GBN, ML / GBM);          // (8, 64)
        gemm_f16<<<go, 256>>>(ab, wo, out, ML, DD, DD, 0, nullptr, nullptr);
    }
}